// round 5
// baseline (speedup 1.0000x reference)
#include <cuda_runtime.h>
#include <math.h>

// Problem constants
#define Bc 4
#define Sc 4
#define Cc 4
#define Lc 512
#define Ec 64
#define Ac 32
#define Hc 8
#define Kc (Sc*Lc + Cc)   // 2052
#define HAc (Hc*Ac)       // 256
#define SCALEF 0.17677669529663687f  // 1/sqrt(32)
#define CSPL 16           // key splits for constants attention
#define ZSPL 4            // chunk-parity splits for sequence attention

typedef unsigned long long u64;

// ---- packed f32x2 helpers (sm_103a FFMA2 path) ------------------------------
__device__ __forceinline__ u64 pack2(float x, float y) {
    u64 r; asm("mov.b64 %0,{%1,%2};" : "=l"(r) : "f"(x), "f"(y)); return r;
}
__device__ __forceinline__ void unpack2(u64 v, float& x, float& y) {
    asm("mov.b64 {%0,%1},%2;" : "=f"(x), "=f"(y) : "l"(v));
}
__device__ __forceinline__ void fma2(u64& d, u64 a, u64 b) {
    asm("fma.rn.f32x2 %0,%1,%2,%0;" : "+l"(d) : "l"(a), "l"(b));
}
__device__ __forceinline__ void cp_async16(void* dst, const void* src) {
    unsigned d = (unsigned)__cvta_generic_to_shared(dst);
    asm volatile("cp.async.cg.shared.global [%0], [%1], 16;" :: "r"(d), "l"(src));
}

// ---------------- scratch (device globals; no allocations allowed) ----------
__device__ float g_q_s  [Bc*Sc*Hc*Lc*Ac];       // [B,S,H,L,A]
__device__ float g_k_all[Bc*Hc*Kc*Ac];          // [B,H,K,A]
__device__ float g_v_all[Bc*Hc*Kc*Ac];          // [B,H,K,A]
__device__ float g_qc   [Bc*Cc*Hc*Ac];          // [B,C,H,A]
__device__ float g_part [ZSPL*Bc*Sc*Hc*Lc*Ac];  // seq split partial acc
__device__ float g_plsum[ZSPL*Bc*Sc*Hc*Lc];     // seq split partial lsum
__device__ float g_cpart[CSPL][Bc*Cc*Hc][33];   // con partials: 32 acc + lsum
__device__ float g_out_s[Bc*Sc*Lc*HAc];         // [B,S,L,H*A]

#define NQ    (Bc*Sc*Hc*Lc)        // 131072 queries
#define PARTF (Bc*Sc*Hc*Lc*Ac)     // floats per seq split

// ---------------- 1) sequence QKV projections (f32x2) ------------------------
__global__ void proj_seq_kernel(
    const float* __restrict__ xq, const float* __restrict__ xk, const float* __restrict__ xv,
    const float* __restrict__ wq, const float* __restrict__ wk, const float* __restrict__ wv)
{
    const int h = blockIdx.x % Hc;
    const int s = (blockIdx.x / Hc) % Sc;
    const int b = blockIdx.x / (Sc*Hc);
    const int l0 = blockIdx.y * 128;
    const int which = blockIdx.z;

    const float* x = (which==0) ? xq : (which==1) ? xk : xv;
    const float* w = (which==0) ? wq : (which==1) ? wk : wv;

    __shared__ float Xs[128][64];   // 32KB
    __shared__ float Wt[32][66];    // transposed weights

    const int tid = threadIdx.x;
    const float* wp = w + (s*Hc + h)*Ec*Ac;
    for (int i = tid; i < Ec*Ac; i += 256)
        Wt[i & 31][i >> 5] = wp[i];
    const float* xp = x + ((b*Sc + s)*Lc + l0)*Ec;
    for (int i = tid; i < 128*Ec/4; i += 256)
        ((float4*)&Xs[0][0])[i] = ((const float4*)xp)[i];
    __syncthreads();

    const int a = tid & 31;
    const int g = tid >> 5;

    u64 acc2[16];
    #pragma unroll
    for (int i = 0; i < 16; i++) acc2[i] = 0ull;

    #pragma unroll
    for (int e = 0; e < Ec; e += 4) {
        const u64 w01 = *(const u64*)&Wt[a][e];
        const u64 w23 = *(const u64*)&Wt[a][e+2];
        #pragma unroll
        for (int i = 0; i < 16; i++) {
            const ulonglong2 x2 = *(const ulonglong2*)&Xs[g*16+i][e];
            fma2(acc2[i], x2.x, w01);
            fma2(acc2[i], x2.y, w23);
        }
    }

    float* op;
    if (which == 0) op = g_q_s + (((b*Sc+s)*Hc + h)*Lc + l0)*Ac;
    else {
        float* base = (which==1) ? g_k_all : g_v_all;
        op = base + ((b*Hc + h)*Kc + (s*Lc + l0))*Ac;
    }
    #pragma unroll
    for (int i = 0; i < 16; i++) {
        float lo, hi; unpack2(acc2[i], lo, hi);
        op[(g*16+i)*Ac + a] = lo + hi;
    }
}

// ---------------- 2) constant QKV projections (tiny) ------------------------
__global__ void proj_con_kernel(
    const float* __restrict__ xq, const float* __restrict__ xk, const float* __restrict__ xv,
    const float* __restrict__ wq, const float* __restrict__ wk, const float* __restrict__ wv)
{
    const int h = blockIdx.x % Hc;
    const int c = (blockIdx.x / Hc) % Cc;
    const int b = blockIdx.x / (Cc*Hc);
    const int which = blockIdx.y;

    const float* x = ((which==0) ? xq : (which==1) ? xk : xv) + (b*Cc + c)*Ec;
    const float* w = ((which==0) ? wq : (which==1) ? wk : wv) + (c*Hc + h)*Ec*Ac;
    const int a = threadIdx.x;

    float acc = 0.f;
    #pragma unroll 8
    for (int e = 0; e < Ec; e++)
        acc += __ldg(&x[e]) * __ldg(&w[e*Ac + a]);

    if (which == 0) g_qc[((b*Cc+c)*Hc + h)*Ac + a] = acc;
    else {
        float* base = (which==1) ? g_k_all : g_v_all;
        base[((b*Hc + h)*Kc + (Sc*Lc + c))*Ac + a] = acc;
    }
}

// ---------------- 3) sequence attention: pair-split, 4-way chunk split -------
// grid: (B*S*H, 8, ZSPL), block 128 = 64 queries x 2 A-halves.
// Thread pair shares query; each owns 16 of A=32. Scores merged via shfl_xor(1).
// Inner loop: 4 keys/iter (independent QK chains, batched shfl+exp).
__global__ void __launch_bounds__(128) attn_seq_kernel(const int* __restrict__ maskp)
{
    __shared__ float4 Ks[2][64][8];   // 16KB
    __shared__ float4 Vs[2][64][8];   // 16KB

    const int tid  = threadIdx.x;
    const int qi   = tid >> 1;       // 0..63
    const int half = tid & 1;        // A-half
    const int bsh  = blockIdx.x;
    const int h    = bsh % Hc;
    const int b    = bsh / (Sc*Hc);
    const int y    = blockIdx.y;     // 0..7 (64-query tiles)
    const int l    = y*64 + qi;
    const int split= blockIdx.z;
    const int msk  = *maskp;

    u64 q2[8];
    {
        const float4* qp = (const float4*)(g_q_s + ((u64)bsh*Lc + l)*Ac + half*16);
        #pragma unroll
        for (int j = 0; j < 4; j++) {
            const float4 v = qp[j];
            q2[2*j]   = pack2(v.x*SCALEF, v.y*SCALEF);
            q2[2*j+1] = pack2(v.z*SCALEF, v.w*SCALEF);
        }
    }

    float lsum = 0.f;
    u64 acc2[8];
    #pragma unroll
    for (int i = 0; i < 8; i++) acc2[i] = 0ull;

    const float4* kb = (const float4*)(g_k_all + (b*Hc + h)*Kc*Ac);
    const float4* vb = (const float4*)(g_v_all + (b*Hc + h)*Kc*Ac);

    // chunk c (0..32): seq chunks (s = c>>3, offset 64*(c&7)); 32 = const (4 keys)
    #define CH_VALID(c) ((c) == 32 || !msk || ((c) & 7) <= y)

    int c = split;
    while (c <= 32 && !CH_VALID(c)) c += ZSPL;
    int st = 0;

    if (c <= 32) {
        const int nk = (c == 32) ? 4 : 64;
        for (int i = tid; i < nk*8; i += 128) {
            cp_async16(&Ks[st][i>>3][i&7], &kb[(c*64)*8 + i]);
            cp_async16(&Vs[st][i>>3][i&7], &vb[(c*64)*8 + i]);
        }
    }
    asm volatile("cp.async.commit_group;");

    while (c <= 32) {
        int nc = c + ZSPL;
        while (nc <= 32 && !CH_VALID(nc)) nc += ZSPL;

        if (nc <= 32) {
            const int nk2 = (nc == 32) ? 4 : 64;
            for (int i = tid; i < nk2*8; i += 128) {
                cp_async16(&Ks[st^1][i>>3][i&7], &kb[(nc*64)*8 + i]);
                cp_async16(&Vs[st^1][i>>3][i&7], &vb[(nc*64)*8 + i]);
            }
            asm volatile("cp.async.commit_group;");
            asm volatile("cp.async.wait_group 1;");
        } else {
            asm volatile("cp.async.commit_group;");
            asm volatile("cp.async.wait_group 0;");
        }
        __syncthreads();

        const int nk = (c == 32) ? 4 : 64;
        int kklim = nk;
        if (msk && c < 32) {
            const int k0c = 64*(c & 7);
            kklim = l - k0c + 1;
            if (kklim > nk) kklim = nk;
            if (kklim < 0)  kklim = 0;
        }

        for (int kk = 0; kk < nk; kk += 4) {
            float s[4];
            #pragma unroll
            for (int i = 0; i < 4; i++) {
                const ulonglong2* kr = (const ulonglong2*)&Ks[st][kk+i][half*4];
                u64 sa = 0ull, sb = 0ull;
                #pragma unroll
                for (int j = 0; j < 2; j++) {
                    const ulonglong2 t0 = kr[2*j], t1 = kr[2*j+1];
                    fma2(sa, q2[4*j],   t0.x); fma2(sb, q2[4*j+1], t0.y);
                    fma2(sa, q2[4*j+2], t1.x); fma2(sb, q2[4*j+3], t1.y);
                }
                float a0,a1,a2,a3;
                unpack2(sa,a0,a1); unpack2(sb,a2,a3);
                s[i] = (a0+a1)+(a2+a3);
            }
            #pragma unroll
            for (int i = 0; i < 4; i++)
                s[i] += __shfl_xor_sync(0xffffffffu, s[i], 1);
            float p[4];
            #pragma unroll
            for (int i = 0; i < 4; i++)
                p[i] = (kk+i < kklim) ? __expf(s[i]) : 0.f;
            lsum += (p[0]+p[1]) + (p[2]+p[3]);
            #pragma unroll
            for (int i = 0; i < 4; i++) {
                const u64 pp = pack2(p[i], p[i]);
                const ulonglong2* vr = (const ulonglong2*)&Vs[st][kk+i][half*4];
                #pragma unroll
                for (int j = 0; j < 2; j++) {
                    const ulonglong2 t0 = vr[2*j], t1 = vr[2*j+1];
                    fma2(acc2[4*j],   pp, t0.x); fma2(acc2[4*j+1], pp, t0.y);
                    fma2(acc2[4*j+2], pp, t1.x); fma2(acc2[4*j+3], pp, t1.y);
                }
            }
        }
        __syncthreads();
        st ^= 1; c = nc;
    }
    #undef CH_VALID

    float4* op = (float4*)(g_part + (u64)split*PARTF + ((u64)bsh*Lc + l)*Ac + half*16);
    #pragma unroll
    for (int j = 0; j < 4; j++) {
        float x0,x1,x2v,x3;
        unpack2(acc2[2*j],   x0, x1);
        unpack2(acc2[2*j+1], x2v, x3);
        float4 o; o.x = x0; o.y = x1; o.z = x2v; o.w = x3;
        op[j] = o;
    }
    if (half == 0)
        g_plsum[split*NQ + bsh*Lc + l] = lsum;
}

// ---------------- combine: fold the ZSPL K-splits ----------------------------
__global__ void combine_kernel()
{
    const int idx4 = blockIdx.x * 256 + threadIdx.x;   // float4 index
    const int row = idx4 >> 3;                          // bsh*512 + l

    float4 a0 = ((const float4*)g_part)[idx4];
    float ls = __ldg(&g_plsum[row]);
    #pragma unroll
    for (int sp = 1; sp < ZSPL; sp++) {
        const float4 a1 = ((const float4*)g_part)[idx4 + sp*(PARTF/4)];
        a0.x += a1.x; a0.y += a1.y; a0.z += a1.z; a0.w += a1.w;
        ls += __ldg(&g_plsum[row + sp*NQ]);
    }
    const float inv = 1.f / ls;

    const int a4  = (idx4 & 7) * 4;
    const int l   = row & (Lc-1);
    const int bsh = row >> 9;
    const int h   = bsh & 7;
    const int bs  = bsh >> 3;

    float4 o;
    o.x = a0.x*inv; o.y = a0.y*inv; o.z = a0.z*inv; o.w = a0.w*inv;
    *(float4*)(g_out_s + ((u64)(bs*Lc + l))*HAc + h*Ac + a4) = o;
}

// ---------------- 4) constants attention: 16-way key split, 8-deep MLP -------
// grid (128, 16), block 64 (2 warps). lane = A index; 8 keys in flight.
__global__ void __launch_bounds__(64) attn_con_kernel()
{
    const int tid = threadIdx.x;
    const int w = tid >> 5, lane = tid & 31;
    const int bch = blockIdx.x;                 // (b*Cc+c)*Hc + h
    const int h = bch % Hc;
    const int b = bch / (Cc*Hc);
    const int split = blockIdx.y;

    const float qa = g_qc[bch*Ac + lane] * SCALEF;
    const float* kb = g_k_all + (b*Hc + h)*Kc*Ac;
    const float* vb = g_v_all + (b*Hc + h)*Kc*Ac;

    const int kstart = split * 129;
    const int kend   = (kstart + 129 < Kc) ? (kstart + 129) : Kc;

    float lsum = 0.f, acc = 0.f;

    for (int k0 = kstart + w*8; k0 < kend; k0 += 16) {
        float sc[8], vv[8];
        #pragma unroll
        for (int i = 0; i < 8; i++) {
            const int k = k0 + i;
            const bool ok = (k < kend);
            const float kv = ok ? __ldg(&kb[k*Ac + lane]) : 0.f;
            vv[i] = ok ? __ldg(&vb[k*Ac + lane]) : 0.f;
            sc[i] = qa * kv;
        }
        #pragma unroll
        for (int off = 16; off > 0; off >>= 1) {
            #pragma unroll
            for (int i = 0; i < 8; i++)
                sc[i] += __shfl_xor_sync(0xffffffff, sc[i], off);
        }
        #pragma unroll
        for (int i = 0; i < 8; i++) {
            const float p = (k0 + i < kend) ? __expf(sc[i]) : 0.f;
            lsum += p;
            acc += p * vv[i];
        }
    }

    __shared__ float sacc[2][32];
    __shared__ float sls[2];
    sacc[w][lane] = acc;
    if (lane == 0) sls[w] = lsum;
    __syncthreads();
    if (w == 0) {
        g_cpart[split][bch][lane] = sacc[0][lane] + sacc[1][lane];
        if (lane == 0) g_cpart[split][bch][32] = sls[0] + sls[1];
    }
}

// ---------------- 5) sequence head projection (f32x2) ------------------------
__global__ void head_seq_kernel(const float* __restrict__ hw, float* __restrict__ out)
{
    const int s = blockIdx.x % Sc;
    const int b = blockIdx.x / Sc;
    const int l0 = blockIdx.y * 64;

    __shared__ float Xc[64][64];
    __shared__ float Wt[64][66];

    const int tid = threadIdx.x;
    const int e = tid % 64;
    const int g = tid / 64;

    u64 acc2[16];
    #pragma unroll
    for (int i = 0; i < 16; i++) acc2[i] = 0ull;

    const float* xbase = g_out_s + ((b*Sc + s)*Lc + l0)*HAc;
    const float* wbase = hw + s*HAc*Ec;

    for (int f0 = 0; f0 < HAc; f0 += 64) {
        __syncthreads();
        for (int i = tid; i < 64*64; i += 256) {
            const int f = i >> 6, ee = i & 63;
            Wt[ee][f] = wbase[(f0 + f)*Ec + ee];
        }
        for (int i = tid; i < 64*64/4; i += 256) {
            const int r = i >> 4, c4 = i & 15;
            *((float4*)&Xc[r][c4*4]) = *(const float4*)(xbase + r*HAc + f0 + c4*4);
        }
        __syncthreads();

        #pragma unroll
        for (int f = 0; f < 64; f += 4) {
            const u64 w01 = *(const u64*)&Wt[e][f];
            const u64 w23 = *(const u64*)&Wt[e][f+2];
            #pragma unroll
            for (int i = 0; i < 16; i++) {
                const ulonglong2 x2 = *(const ulonglong2*)&Xc[g*16+i][f];
                fma2(acc2[i], x2.x, w01);
                fma2(acc2[i], x2.y, w23);
            }
        }
    }

    float* op = out + ((b*Sc + s)*Lc + l0)*Ec;
    #pragma unroll
    for (int i = 0; i < 16; i++) {
        float lo, hi; unpack2(acc2[i], lo, hi);
        op[(g*16+i)*Ec + e] = lo + hi;
    }
}

// ---------------- 6) constants head projection + partial fold ----------------
__global__ void head_con_kernel(const float* __restrict__ hw, float* __restrict__ out)
{
    __shared__ float xs[HAc];
    const int bc = blockIdx.x;       // b*Cc + c
    const int tid = threadIdx.x;

    for (int f = tid; f < HAc; f += 64) {
        const int hh = f >> 5, a = f & 31;
        const int bch = bc*Hc + hh;
        float accs = 0.f, ls = 0.f;
        #pragma unroll
        for (int sp = 0; sp < CSPL; sp++) {
            accs += g_cpart[sp][bch][a];
            ls   += g_cpart[sp][bch][32];
        }
        xs[f] = accs / ls;
    }
    __syncthreads();

    const int e = tid;
    const float* w = hw + (bc % Cc)*HAc*Ec;
    float acc = 0.f;
    #pragma unroll 8
    for (int f = 0; f < HAc; f++)
        acc += xs[f] * __ldg(&w[f*Ec + e]);
    out[bc*Ec + e] = acc;
}

// ---------------- launch -----------------------------------------------------
extern "C" void kernel_launch(void* const* d_in, const int* in_sizes, int n_in,
                              void* d_out, int out_size)
{
    const float* qs  = (const float*)d_in[0];
    const float* ks  = (const float*)d_in[1];
    const float* vs  = (const float*)d_in[2];
    const float* qc  = (const float*)d_in[3];
    const float* kc  = (const float*)d_in[4];
    const float* vc  = (const float*)d_in[5];
    const float* qws = (const float*)d_in[6];
    const float* kws = (const float*)d_in[7];
    const float* vws = (const float*)d_in[8];
    const float* qwc = (const float*)d_in[9];
    const float* kwc = (const float*)d_in[10];
    const float* vwc = (const float*)d_in[11];
    const float* hws = (const float*)d_in[12];
    const float* hwc = (const float*)d_in[13];
    const int*  mask = (const int*)d_in[14];

    float* out = (float*)d_out;
    float* seq_out = out;                     // [B,S,L,E]
    float* con_out = out + Bc*Sc*Lc*Ec;       // [B,C,1,E]

    proj_seq_kernel<<<dim3(Bc*Sc*Hc, Lc/128, 3), 256>>>(qs, ks, vs, qws, kws, vws);
    proj_con_kernel<<<dim3(Bc*Cc*Hc, 3), 32>>>(qc, kc, vc, qwc, kwc, vwc);
    attn_seq_kernel<<<dim3(Bc*Sc*Hc, 8, ZSPL), 128>>>(mask);
    attn_con_kernel<<<dim3(Bc*Cc*Hc, CSPL), 64>>>();
    combine_kernel<<<NQ*8/256, 256>>>();
    head_seq_kernel<<<dim3(Bc*Sc, Lc/64), 256>>>(hws, seq_out);
    head_con_kernel<<<Bc*Cc, 64>>>(hwc, con_out);
}

// round 7
// speedup vs baseline: 1.3137x; 1.3137x over previous
#include <cuda_runtime.h>
#include <math.h>

// Problem constants
#define Bc 4
#define Sc 4
#define Cc 4
#define Lc 512
#define Ec 64
#define Ac 32
#define Hc 8
#define Kc (Sc*Lc + Cc)   // 2052
#define HAc (Hc*Ac)       // 256
#define SCALEF 0.17677669529663687f  // 1/sqrt(32)
#define CSPL 32           // key splits for constants attention

typedef unsigned long long u64;

// ---- packed f32x2 helpers (sm_103a FFMA2 path) ------------------------------
__device__ __forceinline__ u64 pack2(float x, float y) {
    u64 r; asm("mov.b64 %0,{%1,%2};" : "=l"(r) : "f"(x), "f"(y)); return r;
}
__device__ __forceinline__ void unpack2(u64 v, float& x, float& y) {
    asm("mov.b64 {%0,%1},%2;" : "=f"(x), "=f"(y) : "l"(v));
}
__device__ __forceinline__ void fma2(u64& d, u64 a, u64 b) {
    asm("fma.rn.f32x2 %0,%1,%2,%0;" : "+l"(d) : "l"(a), "l"(b));
}
__device__ __forceinline__ void cp_async16(void* dst, const void* src) {
    unsigned d = (unsigned)__cvta_generic_to_shared(dst);
    asm volatile("cp.async.cg.shared.global [%0], [%1], 16;" :: "r"(d), "l"(src));
}

// ---------------- scratch (device globals; no allocations allowed) ----------
__device__ float g_q_s  [Bc*Sc*Hc*Lc*Ac];     // [B,S,H,L,A]
__device__ float g_k_all[Bc*Hc*Kc*Ac];        // [B,H,K,A]
__device__ float g_v_all[Bc*Hc*Kc*Ac];        // [B,H,K,A]
__device__ float g_qc   [Bc*Cc*Hc*Ac];        // [B,C,H,A]
__device__ float g_part [2*Bc*Sc*Hc*Lc*Ac];   // seq split partial acc
__device__ float g_plsum[2*Bc*Sc*Hc*Lc];      // seq split partial lsum
__device__ float g_cpart[CSPL][Bc*Cc*Hc][33]; // con partials: 32 acc + lsum
__device__ float g_out_s[Bc*Sc*Lc*HAc];       // [B,S,L,H*A]

#define NQ    (Bc*Sc*Hc*Lc)        // 131072 queries
#define PARTF (Bc*Sc*Hc*Lc*Ac)     // floats per seq split

// ---------------- 1) sequence QKV projections (f32x2) ------------------------
// grid: (B*S*H, L/128, 3), block 256. (q/k/v use DIFFERENT input tensors.)
__global__ void proj_seq_kernel(
    const float* __restrict__ xq, const float* __restrict__ xk, const float* __restrict__ xv,
    const float* __restrict__ wq, const float* __restrict__ wk, const float* __restrict__ wv)
{
    const int h = blockIdx.x % Hc;
    const int s = (blockIdx.x / Hc) % Sc;
    const int b = blockIdx.x / (Sc*Hc);
    const int l0 = blockIdx.y * 128;
    const int which = blockIdx.z;

    const float* x = (which==0) ? xq : (which==1) ? xk : xv;
    const float* w = (which==0) ? wq : (which==1) ? wk : wv;

    __shared__ float Xs[128][64];   // 32KB
    __shared__ float Wt[32][66];    // transposed weights

    const int tid = threadIdx.x;
    const float* wp = w + (s*Hc + h)*Ec*Ac;
    for (int i = tid; i < Ec*Ac; i += 256)
        Wt[i & 31][i >> 5] = wp[i];
    const float* xp = x + ((b*Sc + s)*Lc + l0)*Ec;
    for (int i = tid; i < 128*Ec/4; i += 256)
        ((float4*)&Xs[0][0])[i] = ((const float4*)xp)[i];
    __syncthreads();

    const int a = tid & 31;
    const int g = tid >> 5;

    u64 acc2[16];
    #pragma unroll
    for (int i = 0; i < 16; i++) acc2[i] = 0ull;

    #pragma unroll
    for (int e = 0; e < Ec; e += 4) {
        const u64 w01 = *(const u64*)&Wt[a][e];
        const u64 w23 = *(const u64*)&Wt[a][e+2];
        #pragma unroll
        for (int i = 0; i < 16; i++) {
            const ulonglong2 x2 = *(const ulonglong2*)&Xs[g*16+i][e];
            fma2(acc2[i], x2.x, w01);
            fma2(acc2[i], x2.y, w23);
        }
    }

    float* op;
    if (which == 0) op = g_q_s + (((b*Sc+s)*Hc + h)*Lc + l0)*Ac;
    else {
        float* base = (which==1) ? g_k_all : g_v_all;
        op = base + ((b*Hc + h)*Kc + (s*Lc + l0))*Ac;
    }
    #pragma unroll
    for (int i = 0; i < 16; i++) {
        float lo, hi; unpack2(acc2[i], lo, hi);
        op[(g*16+i)*Ac + a] = lo + hi;
    }
}

// ---------------- 2) constant QKV projections (tiny) ------------------------
__global__ void proj_con_kernel(
    const float* __restrict__ xq, const float* __restrict__ xk, const float* __restrict__ xv,
    const float* __restrict__ wq, const float* __restrict__ wk, const float* __restrict__ wv)
{
    const int h = blockIdx.x % Hc;
    const int c = (blockIdx.x / Hc) % Cc;
    const int b = blockIdx.x / (Cc*Hc);
    const int which = blockIdx.y;

    const float* x = ((which==0) ? xq : (which==1) ? xk : xv) + (b*Cc + c)*Ec;
    const float* w = ((which==0) ? wq : (which==1) ? wk : wv) + (c*Hc + h)*Ec*Ac;
    const int a = threadIdx.x;

    float acc = 0.f;
    #pragma unroll 8
    for (int e = 0; e < Ec; e++)
        acc += __ldg(&x[e]) * __ldg(&w[e*Ac + a]);

    if (which == 0) g_qc[((b*Cc+c)*Hc + h)*Ac + a] = acc;
    else {
        float* base = (which==1) ? g_k_all : g_v_all;
        base[((b*Hc + h)*Kc + (Sc*Lc + c))*Ac + a] = acc;
    }
}

// ---------------- 3) sequence attention: pair-split threads ------------------
// grid: (B*S*H, 8, 2), block 128 = 64 queries x 2 A-halves.
__global__ void __launch_bounds__(128) attn_seq_kernel(const int* __restrict__ maskp)
{
    __shared__ float4 Ks[2][64][8];   // 16KB
    __shared__ float4 Vs[2][64][8];   // 16KB

    const int tid  = threadIdx.x;
    const int qi   = tid >> 1;       // 0..63
    const int half = tid & 1;        // A-half
    const int bsh  = blockIdx.x;
    const int h    = bsh % Hc;
    const int b    = bsh / (Sc*Hc);
    const int y    = blockIdx.y;     // 0..7 (64-query tiles)
    const int l    = y*64 + qi;
    const int split= blockIdx.z;
    const int msk  = *maskp;

    u64 q2[8];
    {
        const float4* qp = (const float4*)(g_q_s + ((u64)bsh*Lc + l)*Ac + half*16);
        #pragma unroll
        for (int j = 0; j < 4; j++) {
            const float4 v = qp[j];
            q2[2*j]   = pack2(v.x*SCALEF, v.y*SCALEF);
            q2[2*j+1] = pack2(v.z*SCALEF, v.w*SCALEF);
        }
    }

    float lsum = 0.f;
    u64 acc2[8];
    #pragma unroll
    for (int i = 0; i < 8; i++) acc2[i] = 0ull;

    const float4* kb = (const float4*)(g_k_all + (b*Hc + h)*Kc*Ac);
    const float4* vb = (const float4*)(g_v_all + (b*Hc + h)*Kc*Ac);

    #define CH_VALID(c) ((c) == 32 || !msk || ((c) & 7) <= y)

    int c = split;
    while (c <= 32 && !CH_VALID(c)) c += 2;
    int st = 0;

    if (c <= 32) {
        const int nk = (c == 32) ? 4 : 64;
        for (int i = tid; i < nk*8; i += 128) {
            cp_async16(&Ks[st][i>>3][i&7], &kb[(c*64)*8 + i]);
            cp_async16(&Vs[st][i>>3][i&7], &vb[(c*64)*8 + i]);
        }
    }
    asm volatile("cp.async.commit_group;");

    while (c <= 32) {
        int nc = c + 2;
        while (nc <= 32 && !CH_VALID(nc)) nc += 2;

        if (nc <= 32) {
            const int nk2 = (nc == 32) ? 4 : 64;
            for (int i = tid; i < nk2*8; i += 128) {
                cp_async16(&Ks[st^1][i>>3][i&7], &kb[(nc*64)*8 + i]);
                cp_async16(&Vs[st^1][i>>3][i&7], &vb[(nc*64)*8 + i]);
            }
            asm volatile("cp.async.commit_group;");
            asm volatile("cp.async.wait_group 1;");
        } else {
            asm volatile("cp.async.commit_group;");
            asm volatile("cp.async.wait_group 0;");
        }
        __syncthreads();

        const int nk = (c == 32) ? 4 : 64;
        int kklim = nk;
        if (msk && c < 32) {
            const int k0c = 64*(c & 7);
            kklim = l - k0c + 1;
            if (kklim > nk) kklim = nk;
            if (kklim < 0)  kklim = 0;
        }

        #pragma unroll 2
        for (int kk = 0; kk < nk; kk += 2) {
            const ulonglong2* kr0 = (const ulonglong2*)&Ks[st][kk][half*4];
            const ulonglong2* kr1 = (const ulonglong2*)&Ks[st][kk+1][half*4];
            u64 sa0=0ull, sb0=0ull, sa1=0ull, sb1=0ull;
            #pragma unroll
            for (int j = 0; j < 2; j++) {
                const ulonglong2 t00 = kr0[2*j], t01 = kr0[2*j+1];
                const ulonglong2 t10 = kr1[2*j], t11 = kr1[2*j+1];
                fma2(sa0, q2[4*j],   t00.x); fma2(sb0, q2[4*j+1], t00.y);
                fma2(sa0, q2[4*j+2], t01.x); fma2(sb0, q2[4*j+3], t01.y);
                fma2(sa1, q2[4*j],   t10.x); fma2(sb1, q2[4*j+1], t10.y);
                fma2(sa1, q2[4*j+2], t11.x); fma2(sb1, q2[4*j+3], t11.y);
            }
            float a0,a1,a2,a3,b0,b1,b2,b3;
            unpack2(sa0,a0,a1); unpack2(sb0,a2,a3);
            unpack2(sa1,b0,b1); unpack2(sb1,b2,b3);
            float s0 = (a0+a1)+(a2+a3);
            float s1 = (b0+b1)+(b2+b3);
            s0 += __shfl_xor_sync(0xffffffffu, s0, 1);
            s1 += __shfl_xor_sync(0xffffffffu, s1, 1);
            const float p0 = (kk   < kklim) ? __expf(s0) : 0.f;
            const float p1 = (kk+1 < kklim) ? __expf(s1) : 0.f;
            lsum += p0 + p1;
            const u64 p02 = pack2(p0, p0);
            const u64 p12 = pack2(p1, p1);
            const ulonglong2* vr0 = (const ulonglong2*)&Vs[st][kk][half*4];
            const ulonglong2* vr1 = (const ulonglong2*)&Vs[st][kk+1][half*4];
            #pragma unroll
            for (int j = 0; j < 2; j++) {
                const ulonglong2 t0 = vr0[2*j], t0b = vr0[2*j+1];
                const ulonglong2 t1 = vr1[2*j], t1b = vr1[2*j+1];
                fma2(acc2[4*j],   p02, t0.x);  fma2(acc2[4*j+1], p02, t0.y);
                fma2(acc2[4*j+2], p02, t0b.x); fma2(acc2[4*j+3], p02, t0b.y);
                fma2(acc2[4*j],   p12, t1.x);  fma2(acc2[4*j+1], p12, t1.y);
                fma2(acc2[4*j+2], p12, t1b.x); fma2(acc2[4*j+3], p12, t1b.y);
            }
        }
        __syncthreads();
        st ^= 1; c = nc;
    }
    #undef CH_VALID

    float4* op = (float4*)(g_part + (u64)split*PARTF + ((u64)bsh*Lc + l)*Ac + half*16);
    #pragma unroll
    for (int j = 0; j < 4; j++) {
        float x0,x1,x2v,x3;
        unpack2(acc2[2*j],   x0, x1);
        unpack2(acc2[2*j+1], x2v, x3);
        float4 o; o.x = x0; o.y = x1; o.z = x2v; o.w = x3;
        op[j] = o;
    }
    if (half == 0)
        g_plsum[split*NQ + bsh*Lc + l] = lsum;
}

// ---------------- combine: fold the two K-splits -----------------------------
__global__ void combine_kernel()
{
    const int idx4 = blockIdx.x * 256 + threadIdx.x;   // float4 index
    const int row = idx4 >> 3;                          // bsh*512 + l
    const float4 a0 = ((const float4*)g_part)[idx4];
    const float4 a1 = ((const float4*)g_part)[idx4 + PARTF/4];
    const float inv = 1.f / (__ldg(&g_plsum[row]) + __ldg(&g_plsum[row + NQ]));

    const int a4  = (idx4 & 7) * 4;
    const int l   = row & (Lc-1);
    const int bsh = row >> 9;
    const int h   = bsh & 7;
    const int bs  = bsh >> 3;

    float4 o;
    o.x = (a0.x + a1.x)*inv; o.y = (a0.y + a1.y)*inv;
    o.z = (a0.z + a1.z)*inv; o.w = (a0.w + a1.w)*inv;
    *(float4*)(g_out_s + ((u64)(bs*Lc + l))*HAc + h*Ac + a4) = o;
}

// ---------------- 4) constants attention: 32-way key split -------------------
// grid (128, 32), block 64 (2 warps). lane = A index; 4 keys in flight.
__global__ void __launch_bounds__(64) attn_con_kernel()
{
    const int tid = threadIdx.x;
    const int w = tid >> 5, lane = tid & 31;
    const int bch = blockIdx.x;                 // (b*Cc+c)*Hc + h
    const int h = bch % Hc;
    const int b = bch / (Cc*Hc);
    const int split = blockIdx.y;

    const float qa = g_qc[bch*Ac + lane] * SCALEF;
    const float* kb = g_k_all + (b*Hc + h)*Kc*Ac;
    const float* vb = g_v_all + (b*Hc + h)*Kc*Ac;

    const int kstart = split * 65;
    const int kend   = (kstart + 65 < Kc) ? (kstart + 65) : Kc;

    float lsum = 0.f, acc = 0.f;

    for (int k0 = kstart + w*4; k0 < kend; k0 += 8) {
        float sc[4], vv[4];
        #pragma unroll
        for (int i = 0; i < 4; i++) {
            const int k = k0 + i;
            const bool ok = (k < kend);
            const float kv = ok ? __ldg(&kb[k*Ac + lane]) : 0.f;
            vv[i] = ok ? __ldg(&vb[k*Ac + lane]) : 0.f;
            sc[i] = qa * kv;
        }
        #pragma unroll
        for (int off = 16; off > 0; off >>= 1) {
            #pragma unroll
            for (int i = 0; i < 4; i++)
                sc[i] += __shfl_xor_sync(0xffffffff, sc[i], off);
        }
        #pragma unroll
        for (int i = 0; i < 4; i++) {
            const float p = (k0 + i < kend) ? __expf(sc[i]) : 0.f;
            lsum += p;
            acc += p * vv[i];
        }
    }

    __shared__ float sacc[2][32];
    __shared__ float sls[2];
    sacc[w][lane] = acc;
    if (lane == 0) sls[w] = lsum;
    __syncthreads();
    if (w == 0) {
        g_cpart[split][bch][lane] = sacc[0][lane] + sacc[1][lane];
        if (lane == 0) g_cpart[split][bch][32] = sls[0] + sls[1];
    }
}

// ---------------- 5) sequence head projection (f32x2) ------------------------
__global__ void head_seq_kernel(const float* __restrict__ hw, float* __restrict__ out)
{
    const int s = blockIdx.x % Sc;
    const int b = blockIdx.x / Sc;
    const int l0 = blockIdx.y * 64;

    __shared__ float Xc[64][64];
    __shared__ float Wt[64][66];

    const int tid = threadIdx.x;
    const int e = tid % 64;
    const int g = tid / 64;

    u64 acc2[16];
    #pragma unroll
    for (int i = 0; i < 16; i++) acc2[i] = 0ull;

    const float* xbase = g_out_s + ((b*Sc + s)*Lc + l0)*HAc;
    const float* wbase = hw + s*HAc*Ec;

    for (int f0 = 0; f0 < HAc; f0 += 64) {
        __syncthreads();
        for (int i = tid; i < 64*64; i += 256) {
            const int f = i >> 6, ee = i & 63;
            Wt[ee][f] = wbase[(f0 + f)*Ec + ee];
        }
        for (int i = tid; i < 64*64/4; i += 256) {
            const int r = i >> 4, c4 = i & 15;
            *((float4*)&Xc[r][c4*4]) = *(const float4*)(xbase + r*HAc + f0 + c4*4);
        }
        __syncthreads();

        #pragma unroll
        for (int f = 0; f < 64; f += 4) {
            const u64 w01 = *(const u64*)&Wt[e][f];
            const u64 w23 = *(const u64*)&Wt[e][f+2];
            #pragma unroll
            for (int i = 0; i < 16; i++) {
                const ulonglong2 x2 = *(const ulonglong2*)&Xc[g*16+i][f];
                fma2(acc2[i], x2.x, w01);
                fma2(acc2[i], x2.y, w23);
            }
        }
    }

    float* op = out + ((b*Sc + s)*Lc + l0)*Ec;
    #pragma unroll
    for (int i = 0; i < 16; i++) {
        float lo, hi; unpack2(acc2[i], lo, hi);
        op[(g*16+i)*Ec + e] = lo + hi;
    }
}

// ---------------- 6) constants head projection + partial fold ----------------
__global__ void head_con_kernel(const float* __restrict__ hw, float* __restrict__ out)
{
    __shared__ float xs[HAc];
    const int bc = blockIdx.x;       // b*Cc + c
    const int tid = threadIdx.x;

    for (int f = tid; f < HAc; f += 64) {
        const int hh = f >> 5, a = f & 31;
        const int bch = bc*Hc + hh;
        float accs = 0.f, ls = 0.f;
        #pragma unroll
        for (int sp = 0; sp < CSPL; sp++) {
            accs += g_cpart[sp][bch][a];
            ls   += g_cpart[sp][bch][32];
        }
        xs[f] = accs / ls;
    }
    __syncthreads();

    const int e = tid;
    const float* w = hw + (bc % Cc)*HAc*Ec;
    float acc = 0.f;
    #pragma unroll 8
    for (int f = 0; f < HAc; f++)
        acc += xs[f] * __ldg(&w[f*Ec + e]);
    out[bc*Ec + e] = acc;
}

// ---------------- launch -----------------------------------------------------
extern "C" void kernel_launch(void* const* d_in, const int* in_sizes, int n_in,
                              void* d_out, int out_size)
{
    const float* qs  = (const float*)d_in[0];
    const float* ks  = (const float*)d_in[1];
    const float* vs  = (const float*)d_in[2];
    const float* qc  = (const float*)d_in[3];
    const float* kc  = (const float*)d_in[4];
    const float* vc  = (const float*)d_in[5];
    const float* qws = (const float*)d_in[6];
    const float* kws = (const float*)d_in[7];
    const float* vws = (const float*)d_in[8];
    const float* qwc = (const float*)d_in[9];
    const float* kwc = (const float*)d_in[10];
    const float* vwc = (const float*)d_in[11];
    const float* hws = (const float*)d_in[12];
    const float* hwc = (const float*)d_in[13];
    const int*  mask = (const int*)d_in[14];

    float* out = (float*)d_out;
    float* seq_out = out;                     // [B,S,L,E]
    float* con_out = out + Bc*Sc*Lc*Ec;       // [B,C,1,E]

    proj_seq_kernel<<<dim3(Bc*Sc*Hc, Lc/128, 3), 256>>>(qs, ks, vs, qws, kws, vws);
    proj_con_kernel<<<dim3(Bc*Cc*Hc, 3), 32>>>(qc, kc, vc, qwc, kwc, vwc);
    attn_seq_kernel<<<dim3(Bc*Sc*Hc, 8, 2), 128>>>(mask);
    attn_con_kernel<<<dim3(Bc*Cc*Hc, CSPL), 64>>>();
    combine_kernel<<<PARTF/4/256, 256>>>();
    head_seq_kernel<<<dim3(Bc*Sc, Lc/64), 256>>>(hws, seq_out);
    head_con_kernel<<<Bc*Cc, 64>>>(hwc, con_out);
}

// round 9
// speedup vs baseline: 2.5773x; 1.9618x over previous
#include <cuda_runtime.h>
#include <math.h>
#include <stdint.h>

// Problem constants
#define Bc 4
#define Sc 4
#define Cc 4
#define Lc 512
#define Ec 64
#define Ac 32
#define Hc 8
#define Kc (Sc*Lc + Cc)   // 2052
#define HAc (Hc*Ac)       // 256
#define SCALEF 0.17677669529663687f  // 1/sqrt(32)
#define CSPL 32           // key splits for constants attention

typedef unsigned long long u64;

// ---- packed f32x2 helpers ----------------------------------------------------
__device__ __forceinline__ u64 pack2(float x, float y) {
    u64 r; asm("mov.b64 %0,{%1,%2};" : "=l"(r) : "f"(x), "f"(y)); return r;
}
__device__ __forceinline__ void unpack2(u64 v, float& x, float& y) {
    asm("mov.b64 {%0,%1},%2;" : "=f"(x), "=f"(y) : "l"(v));
}
__device__ __forceinline__ void fma2(u64& d, u64 a, u64 b) {
    asm("fma.rn.f32x2 %0,%1,%2,%0;" : "+l"(d) : "l"(a), "l"(b));
}
__device__ __forceinline__ void cp_async16_sh(unsigned dst, const void* src) {
    asm volatile("cp.async.cg.shared.global [%0],[%1],16;" :: "r"(dst), "l"(src));
}
__device__ __forceinline__ uint32_t f2tf(float x) {
    uint32_t r; asm("cvt.rna.tf32.f32 %0,%1;" : "=r"(r) : "f"(x)); return r;
}
// m16n8k8 tf32 mma, D==C in-place
__device__ __forceinline__ void mma8(float* d, const uint32_t* a, uint32_t b0, uint32_t b1) {
    asm volatile("mma.sync.aligned.m16n8k8.row.col.f32.tf32.tf32.f32 "
        "{%0,%1,%2,%3},{%4,%5,%6,%7},{%8,%9},{%0,%1,%2,%3};"
        : "+f"(d[0]), "+f"(d[1]), "+f"(d[2]), "+f"(d[3])
        : "r"(a[0]), "r"(a[1]), "r"(a[2]), "r"(a[3]), "r"(b0), "r"(b1));
}

// ---------------- scratch (device globals; no allocations allowed) ----------
__device__ float g_q_s  [Bc*Sc*Hc*Lc*Ac];     // [B,S,H,L,A]
__device__ float g_k_all[Bc*Hc*Kc*Ac];        // [B,H,K,A]
__device__ float g_v_all[Bc*Hc*Kc*Ac];        // [B,H,K,A]
__device__ float g_qc   [Bc*Cc*Hc*Ac];        // [B,C,H,A]
__device__ float g_cpart[CSPL][Bc*Cc*Hc][33]; // con partials: 32 acc + lsum
__device__ float g_out_s[Bc*Sc*Lc*HAc];       // [B,S,L,H*A]

// ---------------- 1) sequence QKV projections (f32x2) ------------------------
__global__ void proj_seq_kernel(
    const float* __restrict__ xq, const float* __restrict__ xk, const float* __restrict__ xv,
    const float* __restrict__ wq, const float* __restrict__ wk, const float* __restrict__ wv)
{
    const int h = blockIdx.x % Hc;
    const int s = (blockIdx.x / Hc) % Sc;
    const int b = blockIdx.x / (Sc*Hc);
    const int l0 = blockIdx.y * 128;
    const int which = blockIdx.z;

    const float* x = (which==0) ? xq : (which==1) ? xk : xv;
    const float* w = (which==0) ? wq : (which==1) ? wk : wv;

    __shared__ float Xs[128][64];
    __shared__ float Wt[32][66];

    const int tid = threadIdx.x;
    const float* wp = w + (s*Hc + h)*Ec*Ac;
    for (int i = tid; i < Ec*Ac; i += 256)
        Wt[i & 31][i >> 5] = wp[i];
    const float* xp = x + ((b*Sc + s)*Lc + l0)*Ec;
    for (int i = tid; i < 128*Ec/4; i += 256)
        ((float4*)&Xs[0][0])[i] = ((const float4*)xp)[i];
    __syncthreads();

    const int a = tid & 31;
    const int g = tid >> 5;

    u64 acc2[16];
    #pragma unroll
    for (int i = 0; i < 16; i++) acc2[i] = 0ull;

    #pragma unroll
    for (int e = 0; e < Ec; e += 4) {
        const u64 w01 = *(const u64*)&Wt[a][e];
        const u64 w23 = *(const u64*)&Wt[a][e+2];
        #pragma unroll
        for (int i = 0; i < 16; i++) {
            const ulonglong2 x2 = *(const ulonglong2*)&Xs[g*16+i][e];
            fma2(acc2[i], x2.x, w01);
            fma2(acc2[i], x2.y, w23);
        }
    }

    float* op;
    if (which == 0) op = g_q_s + (((b*Sc+s)*Hc + h)*Lc + l0)*Ac;
    else {
        float* base = (which==1) ? g_k_all : g_v_all;
        op = base + ((b*Hc + h)*Kc + (s*Lc + l0))*Ac;
    }
    #pragma unroll
    for (int i = 0; i < 16; i++) {
        float lo, hi; unpack2(acc2[i], lo, hi);
        op[(g*16+i)*Ac + a] = lo + hi;
    }
}

// ---------------- 2) constant QKV projections (tiny) ------------------------
__global__ void proj_con_kernel(
    const float* __restrict__ xq, const float* __restrict__ xk, const float* __restrict__ xv,
    const float* __restrict__ wq, const float* __restrict__ wk, const float* __restrict__ wv)
{
    const int h = blockIdx.x % Hc;
    const int c = (blockIdx.x / Hc) % Cc;
    const int b = blockIdx.x / (Cc*Hc);
    const int which = blockIdx.y;

    const float* x = ((which==0) ? xq : (which==1) ? xk : xv) + (b*Cc + c)*Ec;
    const float* w = ((which==0) ? wq : (which==1) ? wk : wv) + (c*Hc + h)*Ec*Ac;
    const int a = threadIdx.x;

    float acc = 0.f;
    #pragma unroll 8
    for (int e = 0; e < Ec; e++)
        acc += __ldg(&x[e]) * __ldg(&w[e*Ac + a]);

    if (which == 0) g_qc[((b*Cc+c)*Hc + h)*Ac + a] = acc;
    else {
        float* base = (which==1) ? g_k_all : g_v_all;
        base[((b*Hc + h)*Kc + (Sc*Lc + c))*Ac + a] = acc;
    }
}

// ---------------- 3) sequence attention: mma.sync tf32 flash -----------------
// grid (B*S*H=128, 8), block 128 (4 warps). Warp owns 16 queries.
// SMEM: K/V double buffer [64][36] each, + P per-warp [16][68].
#define KVROWF 36                       // floats per K/V row (144B, 16B aligned)
#define KVBUFB 18432                    // bytes per buffer (K+V)
#define SM_PB  36864                    // P base byte offset
#define SMEM_MMA (SM_PB + 4*4352)       // 54272 bytes

__device__ __forceinline__ void mma_load_kv(char* smem, int buf,
        const float4* kb4, const float4* vb4, int kb0, int nr, int tid) {
    float* Ksm = (float*)(smem + (u64)buf*KVBUFB);
    float* Vsm = Ksm + 2304;
    #pragma unroll
    for (int it = 0; it < 4; it++) {
        const int i = tid + it*128;        // 0..511
        const int row = i >> 3, f4 = i & 7;
        float* kd = Ksm + row*KVROWF + f4*4;
        float* vd = Vsm + row*KVROWF + f4*4;
        if (row < nr) {
            cp_async16_sh((unsigned)__cvta_generic_to_shared(kd), kb4 + (u64)(kb0+row)*8 + f4);
            cp_async16_sh((unsigned)__cvta_generic_to_shared(vd), vb4 + (u64)(kb0+row)*8 + f4);
        } else {
            *(float4*)kd = make_float4(0.f,0.f,0.f,0.f);
            *(float4*)vd = make_float4(0.f,0.f,0.f,0.f);
        }
    }
}

__global__ void __launch_bounds__(128) attn_seq_mma(const int* __restrict__ maskp)
{
    extern __shared__ char smem[];
    const int tid  = threadIdx.x;
    const int w    = tid >> 5, lane = tid & 31;
    const int g    = lane >> 2, tg = lane & 3;
    const int bsh  = blockIdx.x;
    const int ty   = 7 - blockIdx.y;        // heavy tiles first
    const int h    = bsh & 7;
    const int b    = bsh >> 5;
    const int msk  = *maskp;

    const int l0 = ty*64 + w*16;
    const int r0 = l0 + g, r1 = l0 + g + 8;   // two query rows

    // Q fragments (tf32, pre-scaled), resident for whole kernel
    uint32_t qf[4][4];
    {
        const float* qp = g_q_s + (u64)bsh*Lc*Ac;
        #pragma unroll
        for (int ks = 0; ks < 4; ks++) {
            qf[ks][0] = f2tf(qp[(u64)r0*Ac + ks*8 + tg]     * SCALEF);
            qf[ks][1] = f2tf(qp[(u64)r1*Ac + ks*8 + tg]     * SCALEF);
            qf[ks][2] = f2tf(qp[(u64)r0*Ac + ks*8 + tg + 4] * SCALEF);
            qf[ks][3] = f2tf(qp[(u64)r1*Ac + ks*8 + tg + 4] * SCALEF);
        }
    }

    const float4* kb4 = (const float4*)(g_k_all + (u64)(b*Hc + h)*Kc*Ac);
    const float4* vb4 = (const float4*)(g_v_all + (u64)(b*Hc + h)*Kc*Ac);

    const int ncb = msk ? (ty + 1) : 8;      // 64-key chunks per s-block
    const int nch = 4*ncb + 1;               // + const chunk

    float O[4][4];
    #pragma unroll
    for (int nt = 0; nt < 4; nt++)
        O[nt][0] = O[nt][1] = O[nt][2] = O[nt][3] = 0.f;
    float ls0 = 0.f, ls1 = 0.f;

    float* Pw = (float*)(smem + SM_PB) + w*1088;   // [16][68] this warp

    // chunk 0 load
    {
        int kb0 = 0, nr = 64;
        if (nch == 1) { kb0 = 2048; nr = 4; }
        mma_load_kv(smem, 0, kb4, vb4, kb0, nr, tid);
    }
    asm volatile("cp.async.commit_group;");

    for (int ci = 0; ci < nch; ci++) {
        // prefetch ci+1
        if (ci + 1 < nch) {
            int kb0, nr;
            if (ci + 1 == 4*ncb) { kb0 = 2048; nr = 4; }
            else { const int sk = (ci+1)/ncb, cb = (ci+1)%ncb; kb0 = sk*512 + cb*64; nr = 64; }
            mma_load_kv(smem, (ci+1) & 1, kb4, vb4, kb0, nr, tid);
            asm volatile("cp.async.commit_group;");
            asm volatile("cp.async.wait_group 1;");
        } else {
            asm volatile("cp.async.commit_group;");
            asm volatile("cp.async.wait_group 0;");
        }
        __syncthreads();

        int p0;   // key offset within L block, or -1 for const chunk
        if (ci == 4*ncb) p0 = -1;
        else p0 = (ci % ncb) * 64;

        float* Ksm = (float*)(smem + (u64)(ci & 1)*KVBUFB);
        float* Vsm = Ksm + 2304;

        // ---- QK^T: S[16][64] ----
        float S[8][4];
        #pragma unroll
        for (int nt = 0; nt < 8; nt++)
            S[nt][0] = S[nt][1] = S[nt][2] = S[nt][3] = 0.f;
        #pragma unroll
        for (int ks = 0; ks < 4; ks++) {
            #pragma unroll
            for (int nt = 0; nt < 8; nt++) {
                const float* kp = Ksm + (nt*8 + g)*KVROWF + ks*8 + tg;
                const uint32_t b0 = f2tf(kp[0]);
                const uint32_t b1 = f2tf(kp[4]);
                mma8(S[nt], qf[ks], b0, b1);
            }
        }

        // ---- exp + mask -> P smem ----
        #pragma unroll
        for (int nt = 0; nt < 8; nt++) {
            const int k0 = nt*8 + 2*tg;
            bool v0, v1, v2, v3;
            if (p0 < 0)        { v0 = (k0 < 4); v1 = (k0 < 3); v2 = v0; v3 = v1; }
            else if (!msk)     { v0 = v1 = v2 = v3 = true; }
            else {
                const int kr = p0 + k0;
                v0 = kr <= r0; v1 = kr + 1 <= r0;
                v2 = kr <= r1; v3 = kr + 1 <= r1;
            }
            const float p0e = v0 ? __expf(S[nt][0]) : 0.f;
            const float p1e = v1 ? __expf(S[nt][1]) : 0.f;
            const float p2e = v2 ? __expf(S[nt][2]) : 0.f;
            const float p3e = v3 ? __expf(S[nt][3]) : 0.f;
            ls0 += p0e + p1e;
            ls1 += p2e + p3e;
            *(float2*)(Pw + g*68 + k0)       = make_float2(p0e, p1e);
            *(float2*)(Pw + (g+8)*68 + k0)   = make_float2(p2e, p3e);
        }
        __syncwarp();

        // ---- PV: O[16][32] += P[16][64] * V[64][32] ----
        #pragma unroll
        for (int ks = 0; ks < 8; ks++) {
            uint32_t af[4];
            af[0] = f2tf(Pw[g*68     + ks*8 + tg]);
            af[1] = f2tf(Pw[(g+8)*68 + ks*8 + tg]);
            af[2] = f2tf(Pw[g*68     + ks*8 + tg + 4]);
            af[3] = f2tf(Pw[(g+8)*68 + ks*8 + tg + 4]);
            #pragma unroll
            for (int nt = 0; nt < 4; nt++) {
                const float* vp = Vsm + (ks*8 + tg)*KVROWF + nt*8 + g;
                const uint32_t b0 = f2tf(vp[0]);
                const uint32_t b1 = f2tf(vp[4*KVROWF]);
                mma8(O[nt], af, b0, b1);
            }
        }
        __syncwarp();
        __syncthreads();   // all warps done with this buffer before refill
    }

    // lsum across quad (threads sharing the same rows)
    ls0 += __shfl_xor_sync(0xffffffffu, ls0, 1);
    ls0 += __shfl_xor_sync(0xffffffffu, ls0, 2);
    ls1 += __shfl_xor_sync(0xffffffffu, ls1, 1);
    ls1 += __shfl_xor_sync(0xffffffffu, ls1, 2);
    const float i0 = 1.f / ls0, i1 = 1.f / ls1;

    float* ob = g_out_s + (u64)(bsh >> 3)*Lc*HAc + h*Ac;
    #pragma unroll
    for (int nt = 0; nt < 4; nt++) {
        const int col = nt*8 + 2*tg;
        *(float2*)(ob + (u64)r0*HAc + col) = make_float2(O[nt][0]*i0, O[nt][1]*i0);
        *(float2*)(ob + (u64)r1*HAc + col) = make_float2(O[nt][2]*i1, O[nt][3]*i1);
    }
}

// ---------------- 4) constants attention: 32-way key split -------------------
__global__ void __launch_bounds__(64) attn_con_kernel()
{
    const int tid = threadIdx.x;
    const int w = tid >> 5, lane = tid & 31;
    const int bch = blockIdx.x;
    const int h = bch % Hc;
    const int b = bch / (Cc*Hc);
    const int split = blockIdx.y;

    const float qa = g_qc[bch*Ac + lane] * SCALEF;
    const float* kb = g_k_all + (b*Hc + h)*Kc*Ac;
    const float* vb = g_v_all + (b*Hc + h)*Kc*Ac;

    const int kstart = split * 65;
    const int kend   = (kstart + 65 < Kc) ? (kstart + 65) : Kc;

    float lsum = 0.f, acc = 0.f;

    for (int k0 = kstart + w*4; k0 < kend; k0 += 8) {
        float sc[4], vv[4];
        #pragma unroll
        for (int i = 0; i < 4; i++) {
            const int k = k0 + i;
            const bool ok = (k < kend);
            const float kv = ok ? __ldg(&kb[k*Ac + lane]) : 0.f;
            vv[i] = ok ? __ldg(&vb[k*Ac + lane]) : 0.f;
            sc[i] = qa * kv;
        }
        #pragma unroll
        for (int off = 16; off > 0; off >>= 1) {
            #pragma unroll
            for (int i = 0; i < 4; i++)
                sc[i] += __shfl_xor_sync(0xffffffff, sc[i], off);
        }
        #pragma unroll
        for (int i = 0; i < 4; i++) {
            const float p = (k0 + i < kend) ? __expf(sc[i]) : 0.f;
            lsum += p;
            acc += p * vv[i];
        }
    }

    __shared__ float sacc[2][32];
    __shared__ float sls[2];
    sacc[w][lane] = acc;
    if (lane == 0) sls[w] = lsum;
    __syncthreads();
    if (w == 0) {
        g_cpart[split][bch][lane] = sacc[0][lane] + sacc[1][lane];
        if (lane == 0) g_cpart[split][bch][32] = sls[0] + sls[1];
    }
}

// ---------------- 5) sequence head projection (f32x2) ------------------------
__global__ void head_seq_kernel(const float* __restrict__ hw, float* __restrict__ out)
{
    const int s = blockIdx.x % Sc;
    const int b = blockIdx.x / Sc;
    const int l0 = blockIdx.y * 64;

    __shared__ float Xc[64][64];
    __shared__ float Wt[64][66];

    const int tid = threadIdx.x;
    const int e = tid % 64;
    const int g = tid / 64;

    u64 acc2[16];
    #pragma unroll
    for (int i = 0; i < 16; i++) acc2[i] = 0ull;

    const float* xbase = g_out_s + ((b*Sc + s)*Lc + l0)*HAc;
    const float* wbase = hw + s*HAc*Ec;

    for (int f0 = 0; f0 < HAc; f0 += 64) {
        __syncthreads();
        for (int i = tid; i < 64*64; i += 256) {
            const int f = i >> 6, ee = i & 63;
            Wt[ee][f] = wbase[(f0 + f)*Ec + ee];
        }
        for (int i = tid; i < 64*64/4; i += 256) {
            const int r = i >> 4, c4 = i & 15;
            *((float4*)&Xc[r][c4*4]) = *(const float4*)(xbase + r*HAc + f0 + c4*4);
        }
        __syncthreads();

        #pragma unroll
        for (int f = 0; f < 64; f += 4) {
            const u64 w01 = *(const u64*)&Wt[e][f];
            const u64 w23 = *(const u64*)&Wt[e][f+2];
            #pragma unroll
            for (int i = 0; i < 16; i++) {
                const ulonglong2 x2 = *(const ulonglong2*)&Xc[g*16+i][f];
                fma2(acc2[i], x2.x, w01);
                fma2(acc2[i], x2.y, w23);
            }
        }
    }

    float* op = out + ((b*Sc + s)*Lc + l0)*Ec;
    #pragma unroll
    for (int i = 0; i < 16; i++) {
        float lo, hi; unpack2(acc2[i], lo, hi);
        op[(g*16+i)*Ec + e] = lo + hi;
    }
}

// ---------------- 6) constants head projection + partial fold ----------------
__global__ void head_con_kernel(const float* __restrict__ hw, float* __restrict__ out)
{
    __shared__ float xs[HAc];
    const int bc = blockIdx.x;
    const int tid = threadIdx.x;

    for (int f = tid; f < HAc; f += 64) {
        const int hh = f >> 5, a = f & 31;
        const int bch = bc*Hc + hh;
        float accs = 0.f, ls = 0.f;
        #pragma unroll
        for (int sp = 0; sp < CSPL; sp++) {
            accs += g_cpart[sp][bch][a];
            ls   += g_cpart[sp][bch][32];
        }
        xs[f] = accs / ls;
    }
    __syncthreads();

    const int e = tid;
    const float* w = hw + (bc % Cc)*HAc*Ec;
    float acc = 0.f;
    #pragma unroll 8
    for (int f = 0; f < HAc; f++)
        acc += xs[f] * __ldg(&w[f*Ec + e]);
    out[bc*Ec + e] = acc;
}

// ---------------- launch -----------------------------------------------------
extern "C" void kernel_launch(void* const* d_in, const int* in_sizes, int n_in,
                              void* d_out, int out_size)
{
    const float* qs  = (const float*)d_in[0];
    const float* ks  = (const float*)d_in[1];
    const float* vs  = (const float*)d_in[2];
    const float* qc  = (const float*)d_in[3];
    const float* kc  = (const float*)d_in[4];
    const float* vc  = (const float*)d_in[5];
    const float* qws = (const float*)d_in[6];
    const float* kws = (const float*)d_in[7];
    const float* vws = (const float*)d_in[8];
    const float* qwc = (const float*)d_in[9];
    const float* kwc = (const float*)d_in[10];
    const float* vwc = (const float*)d_in[11];
    const float* hws = (const float*)d_in[12];
    const float* hwc = (const float*)d_in[13];
    const int*  mask = (const int*)d_in[14];

    float* out = (float*)d_out;
    float* seq_out = out;                     // [B,S,L,E]
    float* con_out = out + Bc*Sc*Lc*Ec;       // [B,C,1,E]

    cudaFuncSetAttribute(attn_seq_mma, cudaFuncAttributeMaxDynamicSharedMemorySize, SMEM_MMA);

    proj_seq_kernel<<<dim3(Bc*Sc*Hc, Lc/128, 3), 256>>>(qs, ks, vs, qws, kws, vws);
    proj_con_kernel<<<dim3(Bc*Cc*Hc, 3), 32>>>(qc, kc, vc, qwc, kwc, vwc);
    attn_seq_mma<<<dim3(Bc*Sc*Hc, 8), 128, SMEM_MMA>>>(mask);
    attn_con_kernel<<<dim3(Bc*Cc*Hc, CSPL), 64>>>();
    head_seq_kernel<<<dim3(Bc*Sc, Lc/64), 256>>>(hws, seq_out);
    head_con_kernel<<<Bc*Cc, 64>>>(hwc, con_out);
}

// round 10
// speedup vs baseline: 2.7033x; 1.0489x over previous
#include <cuda_runtime.h>
#include <math.h>
#include <stdint.h>

// Problem constants
#define Bc 4
#define Sc 4
#define Cc 4
#define Lc 512
#define Ec 64
#define Ac 32
#define Hc 8
#define Kc (Sc*Lc + Cc)   // 2052
#define HAc (Hc*Ac)       // 256
#define SCALEF 0.17677669529663687f  // 1/sqrt(32)
#define CSPL 32           // key splits for constants attention

typedef unsigned long long u64;

// ---- packed f32x2 helpers ----------------------------------------------------
__device__ __forceinline__ u64 pack2(float x, float y) {
    u64 r; asm("mov.b64 %0,{%1,%2};" : "=l"(r) : "f"(x), "f"(y)); return r;
}
__device__ __forceinline__ void unpack2(u64 v, float& x, float& y) {
    asm("mov.b64 {%0,%1},%2;" : "=f"(x), "=f"(y) : "l"(v));
}
__device__ __forceinline__ void fma2(u64& d, u64 a, u64 b) {
    asm("fma.rn.f32x2 %0,%1,%2,%0;" : "+l"(d) : "l"(a), "l"(b));
}
__device__ __forceinline__ void cp_async16_sh(unsigned dst, const void* src) {
    asm volatile("cp.async.cg.shared.global [%0],[%1],16;" :: "r"(dst), "l"(src));
}
__device__ __forceinline__ uint32_t f2tf(float x) {
    uint32_t r; asm("cvt.rna.tf32.f32 %0,%1;" : "=r"(r) : "f"(x)); return r;
}
// m16n8k8 tf32 mma, D==C in-place
__device__ __forceinline__ void mma8(float* d, const uint32_t* a, uint32_t b0, uint32_t b1) {
    asm volatile("mma.sync.aligned.m16n8k8.row.col.f32.tf32.tf32.f32 "
        "{%0,%1,%2,%3},{%4,%5,%6,%7},{%8,%9},{%0,%1,%2,%3};"
        : "+f"(d[0]), "+f"(d[1]), "+f"(d[2]), "+f"(d[3])
        : "r"(a[0]), "r"(a[1]), "r"(a[2]), "r"(a[3]), "r"(b0), "r"(b1));
}

// ---------------- scratch (device globals; no allocations allowed) ----------
// NOTE: g_q_s is stored PRE-SCALED (×SCALEF) and tf32-rounded.
//       g_k_all / g_v_all are stored tf32-rounded (fp32 container).
__device__ float g_q_s  [Bc*Sc*Hc*Lc*Ac];     // [B,S,H,L,A]
__device__ float g_k_all[Bc*Hc*Kc*Ac];        // [B,H,K,A]
__device__ float g_v_all[Bc*Hc*Kc*Ac];        // [B,H,K,A]
__device__ float g_qc   [Bc*Cc*Hc*Ac];        // [B,C,H,A] (full fp32)
__device__ float g_cpart[CSPL][Bc*Cc*Hc][33]; // con partials: 32 acc + lsum
__device__ float g_out_s[Bc*Sc*Lc*HAc];       // [B,S,L,H*A]

// ---------------- 1) sequence QKV projections (f32x2, tf32-rounded out) ------
__global__ void proj_seq_kernel(
    const float* __restrict__ xq, const float* __restrict__ xk, const float* __restrict__ xv,
    const float* __restrict__ wq, const float* __restrict__ wk, const float* __restrict__ wv)
{
    const int h = blockIdx.x % Hc;
    const int s = (blockIdx.x / Hc) % Sc;
    const int b = blockIdx.x / (Sc*Hc);
    const int l0 = blockIdx.y * 128;
    const int which = blockIdx.z;

    const float* x = (which==0) ? xq : (which==1) ? xk : xv;
    const float* w = (which==0) ? wq : (which==1) ? wk : wv;

    __shared__ float Xs[128][64];
    __shared__ float Wt[32][66];

    const int tid = threadIdx.x;
    const float* wp = w + (s*Hc + h)*Ec*Ac;
    for (int i = tid; i < Ec*Ac; i += 256)
        Wt[i & 31][i >> 5] = wp[i];
    const float* xp = x + ((b*Sc + s)*Lc + l0)*Ec;
    for (int i = tid; i < 128*Ec/4; i += 256)
        ((float4*)&Xs[0][0])[i] = ((const float4*)xp)[i];
    __syncthreads();

    const int a = tid & 31;
    const int g = tid >> 5;

    u64 acc2[16];
    #pragma unroll
    for (int i = 0; i < 16; i++) acc2[i] = 0ull;

    #pragma unroll
    for (int e = 0; e < Ec; e += 4) {
        const u64 w01 = *(const u64*)&Wt[a][e];
        const u64 w23 = *(const u64*)&Wt[a][e+2];
        #pragma unroll
        for (int i = 0; i < 16; i++) {
            const ulonglong2 x2 = *(const ulonglong2*)&Xs[g*16+i][e];
            fma2(acc2[i], x2.x, w01);
            fma2(acc2[i], x2.y, w23);
        }
    }

    float* op;
    if (which == 0) op = g_q_s + (((b*Sc+s)*Hc + h)*Lc + l0)*Ac;
    else {
        float* base = (which==1) ? g_k_all : g_v_all;
        op = base + ((b*Hc + h)*Kc + (s*Lc + l0))*Ac;
    }
    #pragma unroll
    for (int i = 0; i < 16; i++) {
        float lo, hi; unpack2(acc2[i], lo, hi);
        float o = lo + hi;
        if (which == 0) o *= SCALEF;          // pre-scale Q, then round once
        op[(g*16+i)*Ac + a] = __uint_as_float(f2tf(o));
    }
}

// ---------------- 2) constant QKV projections (tiny) ------------------------
__global__ void proj_con_kernel(
    const float* __restrict__ xq, const float* __restrict__ xk, const float* __restrict__ xv,
    const float* __restrict__ wq, const float* __restrict__ wk, const float* __restrict__ wv)
{
    const int h = blockIdx.x % Hc;
    const int c = (blockIdx.x / Hc) % Cc;
    const int b = blockIdx.x / (Cc*Hc);
    const int which = blockIdx.y;

    const float* x = ((which==0) ? xq : (which==1) ? xk : xv) + (b*Cc + c)*Ec;
    const float* w = ((which==0) ? wq : (which==1) ? wk : wv) + (c*Hc + h)*Ec*Ac;
    const int a = threadIdx.x;

    float acc = 0.f;
    #pragma unroll 8
    for (int e = 0; e < Ec; e++)
        acc += __ldg(&x[e]) * __ldg(&w[e*Ac + a]);

    if (which == 0) g_qc[((b*Cc+c)*Hc + h)*Ac + a] = acc;   // fp32 (con path)
    else {
        float* base = (which==1) ? g_k_all : g_v_all;
        base[((b*Hc + h)*Kc + (Sc*Lc + c))*Ac + a] = __uint_as_float(f2tf(acc));
    }
}

// ---------------- 3) sequence attention: mma.sync tf32 flash -----------------
// grid (B*S*H=128, 8), block 128 (4 warps). Warp owns 16 queries.
// Q/K/V arrive pre-rounded tf32 -> bit-cast straight into mma operands.
#define KVROWF 36                       // floats per K/V row (144B, 16B aligned)
#define KVBUFB 18432                    // bytes per buffer (K+V)
#define SM_PB  36864                    // P base byte offset
#define SMEM_MMA (SM_PB + 4*4352)       // 54272 bytes

__device__ __forceinline__ void mma_load_kv(char* smem, int buf,
        const float4* kb4, const float4* vb4, int kb0, int nr, int tid) {
    float* Ksm = (float*)(smem + (u64)buf*KVBUFB);
    float* Vsm = Ksm + 2304;
    #pragma unroll
    for (int it = 0; it < 4; it++) {
        const int i = tid + it*128;        // 0..511
        const int row = i >> 3, f4 = i & 7;
        float* kd = Ksm + row*KVROWF + f4*4;
        float* vd = Vsm + row*KVROWF + f4*4;
        if (row < nr) {
            cp_async16_sh((unsigned)__cvta_generic_to_shared(kd), kb4 + (u64)(kb0+row)*8 + f4);
            cp_async16_sh((unsigned)__cvta_generic_to_shared(vd), vb4 + (u64)(kb0+row)*8 + f4);
        } else {
            *(float4*)kd = make_float4(0.f,0.f,0.f,0.f);
            *(float4*)vd = make_float4(0.f,0.f,0.f,0.f);
        }
    }
}

__global__ void __launch_bounds__(128) attn_seq_mma(const int* __restrict__ maskp)
{
    extern __shared__ char smem[];
    const int tid  = threadIdx.x;
    const int w    = tid >> 5, lane = tid & 31;
    const int g    = lane >> 2, tg = lane & 3;
    const int bsh  = blockIdx.x;
    const int ty   = 7 - blockIdx.y;        // heavy tiles first
    const int h    = bsh & 7;
    const int b    = bsh >> 5;
    const int msk  = *maskp;

    const int l0 = ty*64 + w*16;
    const int r0 = l0 + g, r1 = l0 + g + 8;   // two query rows

    // Q fragments: pre-scaled, pre-rounded tf32 -> plain bit-cast loads
    uint32_t qf[4][4];
    {
        const float* qp = g_q_s + (u64)bsh*Lc*Ac;
        #pragma unroll
        for (int ks = 0; ks < 4; ks++) {
            qf[ks][0] = __float_as_uint(qp[(u64)r0*Ac + ks*8 + tg]);
            qf[ks][1] = __float_as_uint(qp[(u64)r1*Ac + ks*8 + tg]);
            qf[ks][2] = __float_as_uint(qp[(u64)r0*Ac + ks*8 + tg + 4]);
            qf[ks][3] = __float_as_uint(qp[(u64)r1*Ac + ks*8 + tg + 4]);
        }
    }

    const float4* kb4 = (const float4*)(g_k_all + (u64)(b*Hc + h)*Kc*Ac);
    const float4* vb4 = (const float4*)(g_v_all + (u64)(b*Hc + h)*Kc*Ac);

    const int ncb = msk ? (ty + 1) : 8;      // 64-key chunks per s-block
    const int nch = 4*ncb + 1;               // + const chunk

    float O[4][4];
    #pragma unroll
    for (int nt = 0; nt < 4; nt++)
        O[nt][0] = O[nt][1] = O[nt][2] = O[nt][3] = 0.f;
    float ls0 = 0.f, ls1 = 0.f;

    float* Pw = (float*)(smem + SM_PB) + w*1088;   // [16][68] this warp

    // chunk 0 load
    {
        int kb0 = 0, nr = 64;
        if (nch == 1) { kb0 = 2048; nr = 4; }
        mma_load_kv(smem, 0, kb4, vb4, kb0, nr, tid);
    }
    asm volatile("cp.async.commit_group;");

    for (int ci = 0; ci < nch; ci++) {
        // prefetch ci+1
        if (ci + 1 < nch) {
            int kb0, nr;
            if (ci + 1 == 4*ncb) { kb0 = 2048; nr = 4; }
            else { const int sk = (ci+1)/ncb, cb = (ci+1)%ncb; kb0 = sk*512 + cb*64; nr = 64; }
            mma_load_kv(smem, (ci+1) & 1, kb4, vb4, kb0, nr, tid);
            asm volatile("cp.async.commit_group;");
            asm volatile("cp.async.wait_group 1;");
        } else {
            asm volatile("cp.async.commit_group;");
            asm volatile("cp.async.wait_group 0;");
        }
        __syncthreads();

        int p0;   // key offset within L block, or -1 for const chunk
        if (ci == 4*ncb) p0 = -1;
        else p0 = (ci % ncb) * 64;

        float* Ksm = (float*)(smem + (u64)(ci & 1)*KVBUFB);
        float* Vsm = Ksm + 2304;

        // ---- QK^T: S[16][64] ----
        float S[8][4];
        #pragma unroll
        for (int nt = 0; nt < 8; nt++)
            S[nt][0] = S[nt][1] = S[nt][2] = S[nt][3] = 0.f;
        #pragma unroll
        for (int ks = 0; ks < 4; ks++) {
            #pragma unroll
            for (int nt = 0; nt < 8; nt++) {
                const float* kp = Ksm + (nt*8 + g)*KVROWF + ks*8 + tg;
                const uint32_t b0 = __float_as_uint(kp[0]);
                const uint32_t b1 = __float_as_uint(kp[4]);
                mma8(S[nt], qf[ks], b0, b1);
            }
        }

        // ---- exp + mask -> P smem ----
        #pragma unroll
        for (int nt = 0; nt < 8; nt++) {
            const int k0 = nt*8 + 2*tg;
            bool v0, v1, v2, v3;
            if (p0 < 0)        { v0 = (k0 < 4); v1 = (k0 < 3); v2 = v0; v3 = v1; }
            else if (!msk)     { v0 = v1 = v2 = v3 = true; }
            else {
                const int kr = p0 + k0;
                v0 = kr <= r0; v1 = kr + 1 <= r0;
                v2 = kr <= r1; v3 = kr + 1 <= r1;
            }
            const float p0e = v0 ? __expf(S[nt][0]) : 0.f;
            const float p1e = v1 ? __expf(S[nt][1]) : 0.f;
            const float p2e = v2 ? __expf(S[nt][2]) : 0.f;
            const float p3e = v3 ? __expf(S[nt][3]) : 0.f;
            ls0 += p0e + p1e;
            ls1 += p2e + p3e;
            *(float2*)(Pw + g*68 + k0)       = make_float2(p0e, p1e);
            *(float2*)(Pw + (g+8)*68 + k0)   = make_float2(p2e, p3e);
        }
        __syncwarp();

        // ---- PV: O[16][32] += P[16][64] * V[64][32] ----
        #pragma unroll
        for (int ks = 0; ks < 8; ks++) {
            uint32_t af[4];
            af[0] = f2tf(Pw[g*68     + ks*8 + tg]);
            af[1] = f2tf(Pw[(g+8)*68 + ks*8 + tg]);
            af[2] = f2tf(Pw[g*68     + ks*8 + tg + 4]);
            af[3] = f2tf(Pw[(g+8)*68 + ks*8 + tg + 4]);
            #pragma unroll
            for (int nt = 0; nt < 4; nt++) {
                const float* vp = Vsm + (ks*8 + tg)*KVROWF + nt*8 + g;
                const uint32_t b0 = __float_as_uint(vp[0]);
                const uint32_t b1 = __float_as_uint(vp[4*KVROWF]);
                mma8(O[nt], af, b0, b1);
            }
        }
        __syncwarp();
        __syncthreads();   // all warps done with this buffer before refill
    }

    // lsum across quad (threads sharing the same rows)
    ls0 += __shfl_xor_sync(0xffffffffu, ls0, 1);
    ls0 += __shfl_xor_sync(0xffffffffu, ls0, 2);
    ls1 += __shfl_xor_sync(0xffffffffu, ls1, 1);
    ls1 += __shfl_xor_sync(0xffffffffu, ls1, 2);
    const float i0 = 1.f / ls0, i1 = 1.f / ls1;

    float* ob = g_out_s + (u64)(bsh >> 3)*Lc*HAc + h*Ac;
    #pragma unroll
    for (int nt = 0; nt < 4; nt++) {
        const int col = nt*8 + 2*tg;
        *(float2*)(ob + (u64)r0*HAc + col) = make_float2(O[nt][0]*i0, O[nt][1]*i0);
        *(float2*)(ob + (u64)r1*HAc + col) = make_float2(O[nt][2]*i1, O[nt][3]*i1);
    }
}

// ---------------- 4) constants attention: 32-way key split -------------------
__global__ void __launch_bounds__(64) attn_con_kernel()
{
    const int tid = threadIdx.x;
    const int w = tid >> 5, lane = tid & 31;
    const int bch = blockIdx.x;
    const int h = bch % Hc;
    const int b = bch / (Cc*Hc);
    const int split = blockIdx.y;

    const float qa = g_qc[bch*Ac + lane] * SCALEF;
    const float* kb = g_k_all + (b*Hc + h)*Kc*Ac;
    const float* vb = g_v_all + (b*Hc + h)*Kc*Ac;

    const int kstart = split * 65;
    const int kend   = (kstart + 65 < Kc) ? (kstart + 65) : Kc;

    float lsum = 0.f, acc = 0.f;

    for (int k0 = kstart + w*4; k0 < kend; k0 += 8) {
        float sc[4], vv[4];
        #pragma unroll
        for (int i = 0; i < 4; i++) {
            const int k = k0 + i;
            const bool ok = (k < kend);
            const float kv = ok ? __ldg(&kb[k*Ac + lane]) : 0.f;
            vv[i] = ok ? __ldg(&vb[k*Ac + lane]) : 0.f;
            sc[i] = qa * kv;
        }
        #pragma unroll
        for (int off = 16; off > 0; off >>= 1) {
            #pragma unroll
            for (int i = 0; i < 4; i++)
                sc[i] += __shfl_xor_sync(0xffffffff, sc[i], off);
        }
        #pragma unroll
        for (int i = 0; i < 4; i++) {
            const float p = (k0 + i < kend) ? __expf(sc[i]) : 0.f;
            lsum += p;
            acc += p * vv[i];
        }
    }

    __shared__ float sacc[2][32];
    __shared__ float sls[2];
    sacc[w][lane] = acc;
    if (lane == 0) sls[w] = lsum;
    __syncthreads();
    if (w == 0) {
        g_cpart[split][bch][lane] = sacc[0][lane] + sacc[1][lane];
        if (lane == 0) g_cpart[split][bch][32] = sls[0] + sls[1];
    }
}

// ---------------- 5) sequence head projection (f32x2) ------------------------
__global__ void head_seq_kernel(const float* __restrict__ hw, float* __restrict__ out)
{
    const int s = blockIdx.x % Sc;
    const int b = blockIdx.x / Sc;
    const int l0 = blockIdx.y * 64;

    __shared__ float Xc[64][64];
    __shared__ float Wt[64][66];

    const int tid = threadIdx.x;
    const int e = tid % 64;
    const int g = tid / 64;

    u64 acc2[16];
    #pragma unroll
    for (int i = 0; i < 16; i++) acc2[i] = 0ull;

    const float* xbase = g_out_s + ((b*Sc + s)*Lc + l0)*HAc;
    const float* wbase = hw + s*HAc*Ec;

    for (int f0 = 0; f0 < HAc; f0 += 64) {
        __syncthreads();
        for (int i = tid; i < 64*64; i += 256) {
            const int f = i >> 6, ee = i & 63;
            Wt[ee][f] = wbase[(f0 + f)*Ec + ee];
        }
        for (int i = tid; i < 64*64/4; i += 256) {
            const int r = i >> 4, c4 = i & 15;
            *((float4*)&Xc[r][c4*4]) = *(const float4*)(xbase + r*HAc + f0 + c4*4);
        }
        __syncthreads();

        #pragma unroll
        for (int f = 0; f < 64; f += 4) {
            const u64 w01 = *(const u64*)&Wt[e][f];
            const u64 w23 = *(const u64*)&Wt[e][f+2];
            #pragma unroll
            for (int i = 0; i < 16; i++) {
                const ulonglong2 x2 = *(const ulonglong2*)&Xc[g*16+i][f];
                fma2(acc2[i], x2.x, w01);
                fma2(acc2[i], x2.y, w23);
            }
        }
    }

    float* op = out + ((b*Sc + s)*Lc + l0)*Ec;
    #pragma unroll
    for (int i = 0; i < 16; i++) {
        float lo, hi; unpack2(acc2[i], lo, hi);
        op[(g*16+i)*Ec + e] = lo + hi;
    }
}

// ---------------- 6) constants head projection + partial fold ----------------
__global__ void head_con_kernel(const float* __restrict__ hw, float* __restrict__ out)
{
    __shared__ float xs[HAc];
    const int bc = blockIdx.x;
    const int tid = threadIdx.x;

    for (int f = tid; f < HAc; f += 64) {
        const int hh = f >> 5, a = f & 31;
        const int bch = bc*Hc + hh;
        float accs = 0.f, ls = 0.f;
        #pragma unroll
        for (int sp = 0; sp < CSPL; sp++) {
            accs += g_cpart[sp][bch][a];
            ls   += g_cpart[sp][bch][32];
        }
        xs[f] = accs / ls;
    }
    __syncthreads();

    const int e = tid;
    const float* w = hw + (bc % Cc)*HAc*Ec;
    float acc = 0.f;
    #pragma unroll 8
    for (int f = 0; f < HAc; f++)
        acc += xs[f] * __ldg(&w[f*Ec + e]);
    out[bc*Ec + e] = acc;
}

// ---------------- launch -----------------------------------------------------
extern "C" void kernel_launch(void* const* d_in, const int* in_sizes, int n_in,
                              void* d_out, int out_size)
{
    const float* qs  = (const float*)d_in[0];
    const float* ks  = (const float*)d_in[1];
    const float* vs  = (const float*)d_in[2];
    const float* qc  = (const float*)d_in[3];
    const float* kc  = (const float*)d_in[4];
    const float* vc  = (const float*)d_in[5];
    const float* qws = (const float*)d_in[6];
    const float* kws = (const float*)d_in[7];
    const float* vws = (const float*)d_in[8];
    const float* qwc = (const float*)d_in[9];
    const float* kwc = (const float*)d_in[10];
    const float* vwc = (const float*)d_in[11];
    const float* hws = (const float*)d_in[12];
    const float* hwc = (const float*)d_in[13];
    const int*  mask = (const int*)d_in[14];

    float* out = (float*)d_out;
    float* seq_out = out;                     // [B,S,L,E]
    float* con_out = out + Bc*Sc*Lc*Ec;       // [B,C,1,E]

    cudaFuncSetAttribute(attn_seq_mma, cudaFuncAttributeMaxDynamicSharedMemorySize, SMEM_MMA);

    proj_seq_kernel<<<dim3(Bc*Sc*Hc, Lc/128, 3), 256>>>(qs, ks, vs, qws, kws, vws);
    proj_con_kernel<<<dim3(Bc*Cc*Hc, 3), 32>>>(qc, kc, vc, qwc, kwc, vwc);
    attn_seq_mma<<<dim3(Bc*Sc*Hc, 8), 128, SMEM_MMA>>>(mask);
    attn_con_kernel<<<dim3(Bc*Cc*Hc, CSPL), 64>>>();
    head_seq_kernel<<<dim3(Bc*Sc, Lc/64), 256>>>(hws, seq_out);
    head_con_kernel<<<Bc*Cc, 64>>>(hwc, con_out);
}